// round 12
// baseline (speedup 1.0000x reference)
#include <cuda_runtime.h>
#include <cuda_fp16.h>
#include <cstdint>

// ConvNearestNeightbor: out[b, n*C+c, h, w] = max_k |x_pad[b,c,h-row,w-col] - nb[n,c,k]|
// R12 model: R11 (all-H-ops) was fma-pipe rt-bound (~24K of 26K cyc/SMSP on fma).
// Rebalance: abs via LOP3 (alu), max split 3x HMAX2 (fma) + 5x max.u16x2 (alu; valid
// because post-abs fp16 bit patterns order like u16). fma 24 / alu 28 per iter.

namespace {

constexpr int B = 16, C = 32, H = 32, W = 32, NUM = 32;
constexpr int HW = H * W;
constexpr int NSPLIT = 2;
constexpr int NPER = NUM / NSPLIT;  // 16

__device__ __forceinline__ uint32_t h2bits(__half2 v) {
  return *reinterpret_cast<uint32_t*>(&v);
}
__device__ __forceinline__ __half2 bits2h(uint32_t v) {
  return *reinterpret_cast<__half2*>(&v);
}
// |d| per fp16 lane = clear sign bits -> LOP3 (alu pipe)
__device__ __forceinline__ uint32_t habs_bits(__half2 d) {
  return h2bits(d) & 0x7FFF7FFFu;
}
// packed unsigned 16-bit max -> VIMNMX (alu pipe); exact fp16 max for non-negative values
__device__ __forceinline__ uint32_t umax2(uint32_t a, uint32_t b) {
  uint32_t r;
  asm("max.u16x2 %0, %1, %2;" : "=r"(r) : "r"(a), "r"(b));
  return r;
}
// packed fp16 max -> HMNMX2 (fma pipe)
__device__ __forceinline__ uint32_t hmax2b(uint32_t a, uint32_t b) {
  __half2 r = __hmax2(bits2h(a), bits2h(b));
  return h2bits(r);
}

__global__ __launch_bounds__(256, 6) void cnn_kernel(
    const float* __restrict__ x,
    const float* __restrict__ nb,
    float* __restrict__ out) {
  __shared__ __align__(16) __half xs[34 * 36];     // fp16 halo tile
  __shared__ __align__(16) __half2 nbs[NPER][16];  // duplicated {n,n}, padded row

  const int bc = blockIdx.x;   // 0 .. B*C-1
  const int ns = blockIdx.y;   // 0 .. NSPLIT-1
  const int c  = bc & (C - 1);
  const int b  = bc / C;
  const int tid = threadIdx.x;

  const int h  = tid >> 3;          // 0..31
  const int wq = (tid & 7) << 2;    // 0,4,...,28

  // ---- neighbors first; duplicated into half2 ----
  if (tid < NPER * 9) {
    int nn = tid / 9;
    int k  = tid - nn * 9;
    float v = nb[(size_t)(ns * NPER + nn) * (C * 9) + c * 9 + k];
    nbs[nn][k] = __float2half2_rn(v);
  }

  // ---- x tile: 1 vector LDG per thread -> fp16, + predicated halo zeros ----
  const float* xp = x + (size_t)bc * HW;
  {
    float4 v = *(const float4*)(xp + h * W + wq);
    __half* dst = &xs[(h + 1) * 36 + wq + 1];
    dst[0] = __float2half_rn(v.x);
    dst[1] = __float2half_rn(v.y);
    dst[2] = __float2half_rn(v.z);
    dst[3] = __float2half_rn(v.w);
  }
  if (tid < 132) {  // halo: rows 0,33 cols 0..33; cols 0,33 rows 1..32
    int rr, cc;
    if (tid < 68)        { rr = (tid < 34) ? 0 : 33; cc = (tid < 34) ? tid : tid - 34; }
    else if (tid < 100)  { rr = tid - 68 + 1;  cc = 0; }
    else                 { rr = tid - 100 + 1; cc = 33; }
    *(unsigned short*)&xs[rr * 36 + cc] = 0;
  }
  __syncthreads();

  // ---- window: 5 sliding half2 pairs per row ----
  __half2 pr[3][5];
#pragma unroll
  for (int r = 0; r < 3; r++) {
    const __half2* p = (const __half2*)&xs[(h + r) * 36 + wq];  // 8B-aligned
    __half2 p01 = p[0], p23 = p[1], p45 = p[2];
    pr[r][0] = p01;
    pr[r][2] = p23;
    pr[r][4] = p45;
    pr[r][1] = __halves2half2(__high2half(p01), __low2half(p23));
    pr[r][3] = __halves2half2(__high2half(p23), __low2half(p45));
  }

  float* const outp =
      out + ((size_t)(b * NUM + ns * NPER) * C + c) * HW + h * W + wq;

#pragma unroll 4
  for (int nn = 0; nn < NPER; nn++) {
    __half2 nv[9];
    {
      uint4 c0 = *(const uint4*)&nbs[nn][0];   // k0..k3
      uint4 c1 = *(const uint4*)&nbs[nn][4];   // k4..k7
      nv[0] = bits2h(c0.x); nv[1] = bits2h(c0.y);
      nv[2] = bits2h(c0.z); nv[3] = bits2h(c0.w);
      nv[4] = bits2h(c1.x); nv[5] = bits2h(c1.y);
      nv[6] = bits2h(c1.z); nv[7] = bits2h(c1.w);
      nv[8] = nbs[nn][8];
    }

    uint32_t m[2];  // p=0 -> outputs (0,1); p=1 -> outputs (2,3)
#pragma unroll
    for (int p = 0; p < 2; p++) {
      uint32_t a[9];
#pragma unroll
      for (int k = 0; k < 9; k++) {
        const int r  = 2 - k / 3;
        const int cc = 2 - k % 3;
        a[k] = habs_bits(__hsub2(pr[r][cc + 2 * p], nv[k]));  // HSUB2(fma) + LOP3(alu)
      }
      // fma-pipe tree over taps 0..3 (3x HMNMX2)
      uint32_t hf = hmax2b(hmax2b(a[0], a[1]), hmax2b(a[2], a[3]));
      // alu-pipe tree over taps 4..8 (4x VIMNMX)
      uint32_t uu = umax2(umax2(a[4], a[5]), umax2(a[6], a[7]));
      uu = umax2(uu, a[8]);
      // combine (alu)
      m[p] = umax2(uu, hf);
    }

    float2 f01 = __half22float2(bits2h(m[0]));
    float2 f23 = __half22float2(bits2h(m[1]));
    *(float4*)(outp + (size_t)nn * C * HW) =
        make_float4(f01.x, f01.y, f23.x, f23.y);
  }
}

}  // namespace

extern "C" void kernel_launch(void* const* d_in, const int* in_sizes, int n_in,
                              void* d_out, int out_size) {
  const float* x  = (const float*)d_in[0];   // (B,C,H,W) fp32
  const float* nb = (const float*)d_in[1];   // (NUM,C,9) fp32
  float* out = (float*)d_out;                // (B, NUM*C, H, W) fp32
  dim3 grid(B * C, NSPLIT);
  cnn_kernel<<<grid, 256>>>(x, nb, out);
}